// round 16
// baseline (speedup 1.0000x reference)
#include <cuda_runtime.h>
#include <cuda_fp16.h>
#include <cstdint>

// out[8192,4096] = x[8192,4096] @ tanh(block_diag), 16 blocks of 256x256.
// R13: fp16 m16n8k16. B delivered via FRAGMENT-MAJOR global image (L2-resident,
//      coalesced LDG.128, register double-buffered) -- no smem / no LDSM for B.
//      A staged in smem (2 x 16KB), LDSM as before. CTA 128x256, warp 32x64.
// (R15 = identical resubmit of R13; round 14/15 bench was an infra failure.)

#define NROWS   8192
#define LAYER   4096
#define NBLK    16
#define BSZ     256

// ---------------------------------------------------------------------------
// B fragment image: for (block b, ks 0..15, npg 0..15, lane 0..31) a uint4 =
// the 4 b-fragment words of mma.m16n8k16 for n-tiles {npg*16..+7, +8..+15},
// k = ks*16..+15:
//   w0 = {B[n0+r][k0+2t], B[n0+r][k0+2t+1]}      (r=lane>>2, t=lane&3)
//   w1 = {B[n0+r][k0+8+2t], +1}
//   w2 = {B[n0+8+r][k0+2t], +1}
//   w3 = {B[n0+8+r][k0+8+2t], +1}
// Size: 16 * 16*16*32 * 16B = 2MB (L2-resident).
__device__ __align__(16) uint4 g_Bfrag[NBLK * 8192];

__device__ __forceinline__ uint32_t pack2h(__half lo, __half hi) {
    return (uint32_t)__half_as_ushort(lo) | ((uint32_t)__half_as_ushort(hi) << 16);
}

// prep: 64 CTAs = 16 blocks x 4 kchunks, 256 thr.
__global__ __launch_bounds__(256)
void prep_b_kernel(const float* __restrict__ blocks) {
    __shared__ __half T[256][72];   // [n][k-local], padded rows
    const int cta   = blockIdx.x;
    const int chunk = cta & 3;
    const int b     = cta >> 2;
    const int k0    = chunk * 64;
    const int tid   = threadIdx.x;

    // phase 1: coalesced read + tanh -> T[n][k]
    #pragma unroll
    for (int j = 0; j < 16; j++) {
        int idx = tid + j * 256;          // 0..4095 float4s
        int kk  = idx >> 6;               // 0..63
        int nn  = (idx & 63) * 4;         // 0..252
        const float* p = blocks + (size_t)(b * BSZ + k0 + kk) * LAYER + b * BSZ + nn;
        float4 v = *(const float4*)p;
        T[nn + 0][kk] = __float2half_rn(tanhf(v.x));
        T[nn + 1][kk] = __float2half_rn(tanhf(v.y));
        T[nn + 2][kk] = __float2half_rn(tanhf(v.z));
        T[nn + 3][kk] = __float2half_rn(tanhf(v.w));
    }
    __syncthreads();

    // phase 2: emit fragment records (coalesced uint4 stores)
    #pragma unroll
    for (int j = 0; j < 8; j++) {
        int idx  = tid + j * 256;         // 0..2047
        int lane = idx & 31;
        int npg  = (idx >> 5) & 15;
        int ksl  = idx >> 9;              // 0..3
        int t = lane & 3, r = lane >> 2;
        int n0 = npg * 16, kl = ksl * 16;
        uint4 w;
        w.x = pack2h(T[n0 + r][kl + 2 * t],         T[n0 + r][kl + 2 * t + 1]);
        w.y = pack2h(T[n0 + r][kl + 8 + 2 * t],     T[n0 + r][kl + 8 + 2 * t + 1]);
        w.z = pack2h(T[n0 + 8 + r][kl + 2 * t],     T[n0 + 8 + r][kl + 2 * t + 1]);
        w.w = pack2h(T[n0 + 8 + r][kl + 8 + 2 * t], T[n0 + 8 + r][kl + 8 + 2 * t + 1]);
        g_Bfrag[(size_t)b * 8192 + ((chunk * 4 + ksl) * 16 + npg) * 32 + lane] = w;
    }
}

// ---------------------------------------------------------------------------
__device__ __forceinline__ uint32_t smem_to_u32(const void* p) {
    uint32_t a;
    asm("{ .reg .u64 t; cvta.to.shared.u64 t, %1; cvt.u32.u64 %0, t; }" : "=r"(a) : "l"(p));
    return a;
}
#define LDSM_X4(r0, r1, r2, r3, addr) \
    asm volatile("ldmatrix.sync.aligned.m8n8.x4.shared.b16 {%0,%1,%2,%3}, [%4];" \
                 : "=r"(r0), "=r"(r1), "=r"(r2), "=r"(r3) : "r"(addr))
#define MMA_F16(d, a0, a1, a2, a3, b0, b1) \
    asm volatile("mma.sync.aligned.m16n8k16.row.col.f32.f16.f16.f32 " \
                 "{%0,%1,%2,%3}, {%4,%5,%6,%7}, {%8,%9}, {%0,%1,%2,%3};" \
                 : "+f"((d)[0]), "+f"((d)[1]), "+f"((d)[2]), "+f"((d)[3]) \
                 : "r"(a0), "r"(a1), "r"(a2), "r"(a3), "r"(b0), "r"(b1))

// smem: A only, 2 stages x 16KB
#define STAGE_BYTES 16384
#define SMEM_TOTAL (2 * STAGE_BYTES)

__global__ __launch_bounds__(512, 1)
void bd_mma_kernel(const float* __restrict__ x, float* __restrict__ out) {
    extern __shared__ __align__(128) unsigned char smem[];
    const uint32_t sb = smem_to_u32(smem);

    const int tid  = threadIdx.x;
    const int wid  = tid >> 5;
    const int lane = tid & 31;
    const int wm   = wid >> 2;          // 0..3
    const int wn   = wid & 3;           // 0..3

    const int bid = blockIdx.x;
    const int b   = bid & 15;
    const int mt  = bid >> 4;
    const int rowTile = mt * 128;
    const int kBase   = b * BSZ;
    const int colBase = b * BSZ;

    // A ldmatrix per-lane address components
    const int rA0  = wm * 32 + (lane & 15);
    const int gA   = lane >> 4;
    const int swrA = rA0 & 7;

    float acc[2][8][4];
    #pragma unroll
    for (int i = 0; i < 2; i++)
        #pragma unroll
        for (int j = 0; j < 8; j++)
            #pragma unroll
            for (int e = 0; e < 4; e++) acc[i][j][e] = 0.0f;

    // A writer: 4 threads per row, 16 k-values each
    const int arow = tid >> 2;
    const int kseg = (tid & 3) * 16;
    const float* xrow = x + (size_t)(rowTile + arow) * LAYER + kBase + kseg;

    // B fragment pointer for this warp (npg = wn*4 + np)
    const uint4* bfrag = g_Bfrag + (size_t)b * 8192 + (wn * 4) * 32 + lane;

    float4 xv0, xv1, xv2, xv3;
    uint32_t bb[2][16];   // double-buffered B fragments (one ks each)

#define LOAD_X(c) do { \
        const float4* p = (const float4*)(xrow + (c) * 64); \
        xv0 = p[0]; xv1 = p[1]; xv2 = p[2]; xv3 = p[3]; \
    } while (0)

#define STORE_A(s) do { \
        float4 vv[4] = {xv0, xv1, xv2, xv3}; \
        _Pragma("unroll") \
        for (int j = 0; j < 4; j++) { \
            float4 v = vv[j]; \
            int k = kseg + j * 4; \
            uint2 hp; \
            hp.x = ((uint32_t)__half_as_ushort(__float2half_rn(v.y)) << 16) \
                 | __half_as_ushort(__float2half_rn(v.x)); \
            hp.y = ((uint32_t)__half_as_ushort(__float2half_rn(v.w)) << 16) \
                 | __half_as_ushort(__float2half_rn(v.z)); \
            uint32_t off = (uint32_t)(arow * 128 + (((k >> 3) ^ (arow & 7)) << 4) + (k & 7) * 2); \
            *(uint2*)(smem + (s) * STAGE_BYTES + off) = hp; \
        } \
    } while (0)

#define LOAD_BF(ks, buf) do { \
        const uint4* bp = bfrag + (ks) * 512;  /* (ks*16 npg)*32 */ \
        *(uint4*)&(buf)[0]  = bp[0]; \
        *(uint4*)&(buf)[4]  = bp[32]; \
        *(uint4*)&(buf)[8]  = bp[64]; \
        *(uint4*)&(buf)[12] = bp[96]; \
    } while (0)

    // ---- prologue ----
    LOAD_X(0);
    STORE_A(0);
    LOAD_BF(0, bb[0]);
    __syncthreads();

    // ---- main loop: 4 A-chunks x 4 k16-steps ----
    #pragma unroll
    for (int c = 0; c < 4; c++) {
        const int s = c & 1;
        if (c < 3) LOAD_X(c + 1);
        const uint32_t base = sb + s * STAGE_BYTES;
        #pragma unroll
        for (int ksl = 0; ksl < 4; ksl++) {
            const int ks = c * 4 + ksl;
            if (ks < 15) LOAD_BF(ks + 1, bb[(ks + 1) & 1]);
            const uint32_t axor = (uint32_t)(((2 * ksl + gA) ^ swrA) << 4);
            const uint32_t* bf = bb[ks & 1];
            #pragma unroll
            for (int msub = 0; msub < 2; msub++) {
                uint32_t a[4];
                uint32_t rterm = (uint32_t)((rA0 + msub * 16) * 128);
                LDSM_X4(a[0], a[1], a[2], a[3], base + rterm + axor);
                #pragma unroll
                for (int np = 0; np < 4; np++) {
                    MMA_F16(acc[msub][np * 2],     a[0], a[1], a[2], a[3], bf[np * 4 + 0], bf[np * 4 + 1]);
                    MMA_F16(acc[msub][np * 2 + 1], a[0], a[1], a[2], a[3], bf[np * 4 + 2], bf[np * 4 + 3]);
                }
            }
        }
        if (c < 3) STORE_A(s ^ 1);
        __syncthreads();
    }

    // ---- epilogue ----
    const int g4  = lane >> 2;
    const int tig = lane & 3;
    #pragma unroll
    for (int msub = 0; msub < 2; msub++) {
        int r0 = rowTile + wm * 32 + msub * 16 + g4;
        #pragma unroll
        for (int nsub = 0; nsub < 8; nsub++) {
            int c = colBase + wn * 64 + nsub * 8 + tig * 2;
            float* o0 = out + (size_t)r0 * LAYER + c;
            float* o1 = out + (size_t)(r0 + 8) * LAYER + c;
            *(float2*)o0 = make_float2(acc[msub][nsub][0], acc[msub][nsub][1]);
            *(float2*)o1 = make_float2(acc[msub][nsub][2], acc[msub][nsub][3]);
        }
    }
#undef LOAD_X
#undef STORE_A
#undef LOAD_BF
}

// ---------------------------------------------------------------------------
extern "C" void kernel_launch(void* const* d_in, const int* in_sizes, int n_in,
                              void* d_out, int out_size) {
    const float* x      = (const float*)d_in[0];
    const float* blocks = (const float*)d_in[1];
    float* out = (float*)d_out;

    cudaFuncSetAttribute(bd_mma_kernel,
                         cudaFuncAttributeMaxDynamicSharedMemorySize, SMEM_TOTAL);

    prep_b_kernel<<<64, 256>>>(blocks);
    bd_mma_kernel<<<64 * NBLK, 512, SMEM_TOTAL>>>(x, out);
}